// round 14
// baseline (speedup 1.0000x reference)
#include <cuda_runtime.h>
#include <cuda_fp16.h>
#include <cstdint>

#define N_NODES 100000
#define FEATS   256
#define N_EDGES 3200000
#define CAP     128          // neighbor bucket capacity (Poisson(32): 17-sigma margin)

// Scratch (allocation-free rule: __device__ globals)
__device__ __half g_h[(long long)N_NODES * FEATS];    // linear output h (fp16, 51 MB)
__device__ int    g_idx_is64;                         // 1 if edge_index is int64
__device__ int    g_cnt[N_NODES];                     // per-dest degree (atomic cursors)
__device__ int    g_col[(long long)N_NODES * CAP];    // bucketed neighbor lists (51 MB)

// ---------------------------------------------------------------------------
// zero counts + (block 0) detect edge_index dtype
// ---------------------------------------------------------------------------
__global__ void zero_detect_kernel(const int* __restrict__ ei_words) {
    int i = blockIdx.x * blockDim.x + threadIdx.x;
    if (i < N_NODES) g_cnt[i] = 0;
    if (blockIdx.x == 0 && threadIdx.x < 128) {
        __shared__ int nz;
        if (threadIdx.x == 0) nz = 0;
        __syncthreads();
        int w = ei_words[1 + 2 * threadIdx.x];
        if (w != 0) atomicAdd(&nz, 1);
        __syncthreads();
        if (threadIdx.x == 0) g_idx_is64 = (nz == 0);
    }
}

__device__ __forceinline__ void load_edge(const void* ei, long long e, int& r, int& c) {
    if (g_idx_is64) {
        r = (int)((const long long*)ei)[e];
        c = (int)((const long long*)ei)[N_EDGES + e];
    } else {
        r = ((const int*)ei)[e];
        c = ((const int*)ei)[N_EDGES + e];
    }
}

// ---------------------------------------------------------------------------
// Full 128x128 GEMM tile (double-buffered) — used in K1 only.
// ---------------------------------------------------------------------------
#define GBM 128
#define GBK 32
#define HSTRIDE (GBK + 8)
#define GTILES_HALF ((N_NODES + GBM - 1) / GBM)     // 782 row tiles

__device__ __forceinline__ void mma_f16(float* c, uint32_t a0, uint32_t a1,
                                        uint32_t a2, uint32_t a3,
                                        uint32_t b0, uint32_t b1) {
    asm volatile(
        "mma.sync.aligned.m16n8k16.row.col.f32.f16.f16.f32 "
        "{%0,%1,%2,%3}, {%4,%5,%6,%7}, {%8,%9}, {%0,%1,%2,%3};"
        : "+f"(c[0]), "+f"(c[1]), "+f"(c[2]), "+f"(c[3])
        : "r"(a0), "r"(a1), "r"(a2), "r"(a3), "r"(b0), "r"(b1));
}

__device__ void gemm_tile128(const float* __restrict__ A, const float* __restrict__ W,
                             const float* __restrict__ bias, int tile, int colBase) {
    __shared__ __half As[GBM][HSTRIDE];
    __shared__ __half Bs[128][HSTRIDE];

    const int tid = threadIdx.x;
    const int warp = tid >> 5;
    const int lane = tid & 31;
    const int wm = (warp & 1) * 64;
    const int wn = (warp >> 1) * 32;
    const int grp = lane >> 2;
    const int tig = lane & 3;
    const int rowBase = tile * GBM;

    const int bn  = tid & 127;
    const int bkg = (tid >> 7) * 16;

    float4  avs[4];
    __half2 bvs[8];

    #pragma unroll
    for (int s = 0; s < 4; s++) {
        int f = tid + s * 256;
        int ar = f >> 3, ac4 = (f & 7) * 4;
        int grow = rowBase + ar;
        avs[s] = make_float4(0.f, 0.f, 0.f, 0.f);
        if (grow < N_NODES)
            avs[s] = *reinterpret_cast<const float4*>(A + (long long)grow * FEATS + ac4);
    }
    #pragma unroll
    for (int j = 0; j < 8; j++) {
        float w0 = __ldg(&W[(long long)(bkg + 2 * j) * FEATS + colBase + bn]);
        float w1 = __ldg(&W[(long long)(bkg + 2 * j + 1) * FEATS + colBase + bn]);
        bvs[j] = __floats2half2_rn(w0, w1);
    }

    float acc[4][4][4];
    #pragma unroll
    for (int i = 0; i < 4; i++)
        #pragma unroll
        for (int j = 0; j < 4; j++)
            #pragma unroll
            for (int k = 0; k < 4; k++) acc[i][j][k] = 0.f;

    for (int k0 = 0; k0 < FEATS; k0 += GBK) {
        #pragma unroll
        for (int s = 0; s < 4; s++) {
            int f = tid + s * 256;
            int ar = f >> 3, ac4 = (f & 7) * 4;
            __half2* ap = reinterpret_cast<__half2*>(&As[ar][ac4]);
            ap[0] = __floats2half2_rn(avs[s].x, avs[s].y);
            ap[1] = __floats2half2_rn(avs[s].z, avs[s].w);
        }
        #pragma unroll
        for (int j = 0; j < 8; j++)
            *reinterpret_cast<__half2*>(&Bs[bn][bkg + 2 * j]) = bvs[j];
        __syncthreads();

        int kn = k0 + GBK;
        if (kn < FEATS) {
            #pragma unroll
            for (int s = 0; s < 4; s++) {
                int f = tid + s * 256;
                int ar = f >> 3, ac4 = (f & 7) * 4;
                int grow = rowBase + ar;
                avs[s] = make_float4(0.f, 0.f, 0.f, 0.f);
                if (grow < N_NODES)
                    avs[s] = *reinterpret_cast<const float4*>(A + (long long)grow * FEATS + kn + ac4);
            }
            #pragma unroll
            for (int j = 0; j < 8; j++) {
                float w0 = __ldg(&W[(long long)(kn + bkg + 2 * j) * FEATS + colBase + bn]);
                float w1 = __ldg(&W[(long long)(kn + bkg + 2 * j + 1) * FEATS + colBase + bn]);
                bvs[j] = __floats2half2_rn(w0, w1);
            }
        }

        #pragma unroll
        for (int ks = 0; ks < GBK; ks += 16) {
            uint32_t afr[4][4];
            #pragma unroll
            for (int mi = 0; mi < 4; mi++) {
                int m = wm + mi * 16 + grp;
                afr[mi][0] = *reinterpret_cast<const uint32_t*>(&As[m][ks + 2 * tig]);
                afr[mi][1] = *reinterpret_cast<const uint32_t*>(&As[m + 8][ks + 2 * tig]);
                afr[mi][2] = *reinterpret_cast<const uint32_t*>(&As[m][ks + 2 * tig + 8]);
                afr[mi][3] = *reinterpret_cast<const uint32_t*>(&As[m + 8][ks + 2 * tig + 8]);
            }
            uint32_t bfr[4][2];
            #pragma unroll
            for (int ni = 0; ni < 4; ni++) {
                int n = wn + ni * 8 + grp;
                bfr[ni][0] = *reinterpret_cast<const uint32_t*>(&Bs[n][ks + 2 * tig]);
                bfr[ni][1] = *reinterpret_cast<const uint32_t*>(&Bs[n][ks + 2 * tig + 8]);
            }
            #pragma unroll
            for (int mi = 0; mi < 4; mi++)
                #pragma unroll
                for (int ni = 0; ni < 4; ni++)
                    mma_f16(acc[mi][ni], afr[mi][0], afr[mi][1], afr[mi][2], afr[mi][3],
                            bfr[ni][0], bfr[ni][1]);
        }
        __syncthreads();
    }

    #pragma unroll
    for (int mi = 0; mi < 4; mi++) {
        int row0 = rowBase + wm + mi * 16 + grp;
        int row1 = row0 + 8;
        #pragma unroll
        for (int ni = 0; ni < 4; ni++) {
            int col = colBase + wn + ni * 8 + 2 * tig;
            float b0 = __ldg(&bias[col]);
            float b1 = __ldg(&bias[col + 1]);
            if (row0 < N_NODES) {
                __half2 v = __floats2half2_rn(acc[mi][ni][0] + b0, acc[mi][ni][1] + b1);
                *reinterpret_cast<__half2*>(g_h + (long long)row0 * FEATS + col) = v;
            }
            if (row1 < N_NODES) {
                __half2 v = __floats2half2_rn(acc[mi][ni][2] + b0, acc[mi][ni][3] + b1);
                *reinterpret_cast<__half2*>(g_h + (long long)row1 * FEATS + col) = v;
            }
        }
    }
}

// ---------------------------------------------------------------------------
// Small 128x64 GEMM tile, no double buffer, low-register — used in K2.
// ---------------------------------------------------------------------------
__device__ void gemm_tile64(const float* __restrict__ A, const float* __restrict__ W,
                            const float* __restrict__ bias, int tile, int colBase) {
    __shared__ __half As[GBM][HSTRIDE];
    __shared__ __half Bs[64][HSTRIDE];

    const int tid = threadIdx.x;
    const int warp = tid >> 5;
    const int lane = tid & 31;
    const int wm = (warp & 3) * 32;     // 4 row groups
    const int wn = (warp >> 2) * 32;    // 2 col groups
    const int grp = lane >> 2;
    const int tig = lane & 3;
    const int rowBase = tile * GBM;

    const int bn  = tid & 63;
    const int bkg = (tid >> 6) * 8;     // 4 groups of 8 k

    float acc[2][4][4];
    #pragma unroll
    for (int i = 0; i < 2; i++)
        #pragma unroll
        for (int j = 0; j < 4; j++)
            #pragma unroll
            for (int k = 0; k < 4; k++) acc[i][j][k] = 0.f;

    for (int k0 = 0; k0 < FEATS; k0 += GBK) {
        // A: 128 x 32 floats, 4 float4 per thread, convert+store directly
        #pragma unroll
        for (int s = 0; s < 4; s++) {
            int f = tid + s * 256;
            int ar = f >> 3, ac4 = (f & 7) * 4;
            int grow = rowBase + ar;
            float4 v = make_float4(0.f, 0.f, 0.f, 0.f);
            if (grow < N_NODES)
                v = *reinterpret_cast<const float4*>(A + (long long)grow * FEATS + k0 + ac4);
            __half2* ap = reinterpret_cast<__half2*>(&As[ar][ac4]);
            ap[0] = __floats2half2_rn(v.x, v.y);
            ap[1] = __floats2half2_rn(v.z, v.w);
        }
        // B: 32 k x 64 n; thread owns col bn, 8 k values
        #pragma unroll
        for (int j = 0; j < 4; j++) {
            float w0 = __ldg(&W[(long long)(k0 + bkg + 2 * j) * FEATS + colBase + bn]);
            float w1 = __ldg(&W[(long long)(k0 + bkg + 2 * j + 1) * FEATS + colBase + bn]);
            *reinterpret_cast<__half2*>(&Bs[bn][bkg + 2 * j]) = __floats2half2_rn(w0, w1);
        }
        __syncthreads();

        #pragma unroll
        for (int ks = 0; ks < GBK; ks += 16) {
            uint32_t afr[2][4];
            #pragma unroll
            for (int mi = 0; mi < 2; mi++) {
                int m = wm + mi * 16 + grp;
                afr[mi][0] = *reinterpret_cast<const uint32_t*>(&As[m][ks + 2 * tig]);
                afr[mi][1] = *reinterpret_cast<const uint32_t*>(&As[m + 8][ks + 2 * tig]);
                afr[mi][2] = *reinterpret_cast<const uint32_t*>(&As[m][ks + 2 * tig + 8]);
                afr[mi][3] = *reinterpret_cast<const uint32_t*>(&As[m + 8][ks + 2 * tig + 8]);
            }
            uint32_t bfr[4][2];
            #pragma unroll
            for (int ni = 0; ni < 4; ni++) {
                int n = wn + ni * 8 + grp;
                bfr[ni][0] = *reinterpret_cast<const uint32_t*>(&Bs[n][ks + 2 * tig]);
                bfr[ni][1] = *reinterpret_cast<const uint32_t*>(&Bs[n][ks + 2 * tig + 8]);
            }
            #pragma unroll
            for (int mi = 0; mi < 2; mi++)
                #pragma unroll
                for (int ni = 0; ni < 4; ni++)
                    mma_f16(acc[mi][ni], afr[mi][0], afr[mi][1], afr[mi][2], afr[mi][3],
                            bfr[ni][0], bfr[ni][1]);
        }
        __syncthreads();
    }

    #pragma unroll
    for (int mi = 0; mi < 2; mi++) {
        int row0 = rowBase + wm + mi * 16 + grp;
        int row1 = row0 + 8;
        #pragma unroll
        for (int ni = 0; ni < 4; ni++) {
            int col = colBase + wn + ni * 8 + 2 * tig;
            float b0 = __ldg(&bias[col]);
            float b1 = __ldg(&bias[col + 1]);
            if (row0 < N_NODES) {
                __half2 v = __floats2half2_rn(acc[mi][ni][0] + b0, acc[mi][ni][1] + b1);
                *reinterpret_cast<__half2*>(g_h + (long long)row0 * FEATS + col) = v;
            }
            if (row1 < N_NODES) {
                __half2 v = __floats2half2_rn(acc[mi][ni][2] + b0, acc[mi][ni][3] + b1);
                *reinterpret_cast<__half2*>(g_h + (long long)row1 * FEATS + col) = v;
            }
        }
    }
}

// ---------------------------------------------------------------------------
// Half-row gather: one warp per node, lane owns 4 feats (uint2 fp16).
// ---------------------------------------------------------------------------
__device__ void gather_half(float* __restrict__ out, int node, int lane, int phase) {
    int deg = g_cnt[node];
    int n = deg < CAP ? deg : CAP;
    const int* __restrict__ cols = g_col + (long long)node * CAP;
    const long long foff = phase * 128 + lane * 4;

    float acc[4] = {0.f, 0.f, 0.f, 0.f};

    int i = 0;
    for (; i + 3 < n; i += 4) {
        int c0 = __ldg(&cols[i]);
        int c1 = __ldg(&cols[i + 1]);
        int c2 = __ldg(&cols[i + 2]);
        int c3 = __ldg(&cols[i + 3]);
        uint2 v0 = *reinterpret_cast<const uint2*>(g_h + (long long)c0 * FEATS + foff);
        uint2 v1 = *reinterpret_cast<const uint2*>(g_h + (long long)c1 * FEATS + foff);
        uint2 v2 = *reinterpret_cast<const uint2*>(g_h + (long long)c2 * FEATS + foff);
        uint2 v3 = *reinterpret_cast<const uint2*>(g_h + (long long)c3 * FEATS + foff);
        #pragma unroll
        for (int q = 0; q < 2; q++) {
            float2 f0 = __half22float2(reinterpret_cast<const __half2*>(&v0)[q]);
            float2 f1 = __half22float2(reinterpret_cast<const __half2*>(&v1)[q]);
            float2 f2 = __half22float2(reinterpret_cast<const __half2*>(&v2)[q]);
            float2 f3 = __half22float2(reinterpret_cast<const __half2*>(&v3)[q]);
            acc[2 * q]     += f0.x + f1.x + f2.x + f3.x;
            acc[2 * q + 1] += f0.y + f1.y + f2.y + f3.y;
        }
    }
    for (; i < n; i++) {
        int c0 = __ldg(&cols[i]);
        uint2 v0 = *reinterpret_cast<const uint2*>(g_h + (long long)c0 * FEATS + foff);
        #pragma unroll
        for (int q = 0; q < 2; q++) {
            float2 f0 = __half22float2(reinterpret_cast<const __half2*>(&v0)[q]);
            acc[2 * q]     += f0.x;
            acc[2 * q + 1] += f0.y;
        }
    }

    float inv = deg > 0 ? 1.0f / (float)deg : 0.f;
    float4 o = make_float4(acc[0] * inv, acc[1] * inv, acc[2] * inv, acc[3] * inv);
    __stcs(reinterpret_cast<float4*>(out + (long long)node * FEATS + foff), o);
}

// ---------------------------------------------------------------------------
// K1: fill (full) ∥ gemm cols 0-127. Period 7 = 4 fill + 3 gemm.
// ---------------------------------------------------------------------------
#define FILL_BLOCKS 1024
#define N_PER1 261
#define TOTAL1 (N_PER1 * 7)

__global__ __launch_bounds__(256) void gemm_fill_kernel(const float* __restrict__ A,
                                                        const float* __restrict__ W,
                                                        const float* __restrict__ bias,
                                                        const void* __restrict__ ei) {
    const int period = blockIdx.x / 7;
    const int slot   = blockIdx.x % 7;

    if (slot < 4) {
        int fid = period * 4 + slot;
        if (fid >= FILL_BLOCKS) return;
        long long tbase = (long long)fid * blockDim.x + threadIdx.x;
        long long stride = (long long)FILL_BLOCKS * blockDim.x;
        for (long long e = tbase; e < N_EDGES; e += stride) {
            int r, c;
            load_edge(ei, e, r, c);
            if ((unsigned)r >= N_NODES || (unsigned)c >= N_NODES) continue;
            int pos = atomicAdd(&g_cnt[r], 1);
            if (pos < CAP)
                g_col[(long long)r * CAP + pos] = c;
        }
        return;
    }

    int tile = period * 3 + (slot - 4);
    if (tile >= GTILES_HALF) return;
    gemm_tile128(A, W, bias, tile, 0);
}

// ---------------------------------------------------------------------------
// K2: gather cols 0-127 ∥ gemm cols 128-255 (128x64 tiles).
// Period 9 = 8 gather + 1 gemm; 1564 periods (2 col-subtiles x 782 rows).
// ---------------------------------------------------------------------------
#define GATHER_BLOCKS ((N_NODES + 7) / 8)    // 12500
#define N_PER2 (GTILES_HALF * 2)             // 1564
#define TOTAL2 (N_PER2 * 9)

__global__ __launch_bounds__(256, 4) void gather_gemm_kernel(const float* __restrict__ A,
                                                             const float* __restrict__ W,
                                                             const float* __restrict__ bias,
                                                             float* __restrict__ out) {
    const int period = blockIdx.x / 9;
    const int slot   = blockIdx.x % 9;

    if (slot < 8) {
        int gid = period * 8 + slot;
        if (gid >= GATHER_BLOCKS) return;
        int node = gid * 8 + (threadIdx.x >> 5);
        if (node >= N_NODES) return;
        gather_half(out, node, threadIdx.x & 31, 0);
        return;
    }

    // gemm role: tile index = period (0..1563)
    gemm_tile64(A, W, bias, period >> 1, 128 + (period & 1) * 64);
}

// ---------------------------------------------------------------------------
// K3: gather cols 128-255
// ---------------------------------------------------------------------------
__global__ __launch_bounds__(256) void gather_phase1_kernel(float* __restrict__ out) {
    int node = blockIdx.x * 8 + (threadIdx.x >> 5);
    if (node >= N_NODES) return;
    gather_half(out, node, threadIdx.x & 31, 1);
}

// ---------------------------------------------------------------------------
extern "C" void kernel_launch(void* const* d_in, const int* in_sizes, int n_in,
                              void* d_out, int out_size) {
    const float* x  = (const float*)d_in[0];
    const void*  ei = d_in[1];
    const float* W  = (const float*)d_in[2];
    const float* b  = (const float*)d_in[3];
    float* out = (float*)d_out;

    zero_detect_kernel<<<(N_NODES + 255) / 256, 256>>>((const int*)ei);
    gemm_fill_kernel<<<TOTAL1, 256>>>(x, W, b, ei);
    gather_gemm_kernel<<<TOTAL2, 256>>>(x, W, b, out);
    gather_phase1_kernel<<<GATHER_BLOCKS, 256>>>(out);
}

// round 15
// speedup vs baseline: 1.4547x; 1.4547x over previous
#include <cuda_runtime.h>
#include <cuda_fp16.h>
#include <cstdint>

#define N_NODES 100000
#define FEATS   256
#define N_EDGES 3200000
#define CAP     128          // neighbor bucket capacity (Poisson(32): 17-sigma margin)

// Scratch (allocation-free rule: __device__ globals)
__device__ __half g_h[(long long)N_NODES * FEATS];    // linear output h (fp16, 51 MB)
__device__ int    g_idx_is64;                         // 1 if edge_index is int64
__device__ int    g_cnt[N_NODES];                     // per-dest degree (atomic cursors)
__device__ int    g_col[(long long)N_NODES * CAP];    // bucketed neighbor lists (51 MB)

// ---------------------------------------------------------------------------
// zero counts + (block 0) detect edge_index dtype
// ---------------------------------------------------------------------------
__global__ void zero_detect_kernel(const int* __restrict__ ei_words) {
    int i = blockIdx.x * blockDim.x + threadIdx.x;
    if (i < N_NODES) g_cnt[i] = 0;
    if (blockIdx.x == 0 && threadIdx.x < 128) {
        __shared__ int nz;
        if (threadIdx.x == 0) nz = 0;
        __syncthreads();
        int w = ei_words[1 + 2 * threadIdx.x];
        if (w != 0) atomicAdd(&nz, 1);
        __syncthreads();
        if (threadIdx.x == 0) g_idx_is64 = (nz == 0);
    }
}

__device__ __forceinline__ void load_edge(const void* ei, long long e, int& r, int& c) {
    if (g_idx_is64) {
        r = (int)((const long long*)ei)[e];
        c = (int)((const long long*)ei)[N_EDGES + e];
    } else {
        r = ((const int*)ei)[e];
        c = ((const int*)ei)[N_EDGES + e];
    }
}

// ---------------------------------------------------------------------------
// Single-pass bucket fill (standalone)
// ---------------------------------------------------------------------------
__global__ __launch_bounds__(256) void fill_kernel(const void* __restrict__ ei) {
    long long tbase = (long long)blockIdx.x * blockDim.x + threadIdx.x;
    long long stride = (long long)gridDim.x * blockDim.x;
    for (long long e = tbase; e < N_EDGES; e += stride) {
        int r, c;
        load_edge(ei, e, r, c);
        if ((unsigned)r >= N_NODES || (unsigned)c >= N_NODES) continue;
        int pos = atomicAdd(&g_cnt[r], 1);
        if (pos < CAP)
            g_col[(long long)r * CAP + pos] = c;
    }
}

// ---------------------------------------------------------------------------
// Persistent fp16 GEMM: 148 blocks x 512 threads. Full W (256x256) cached in
// smem fp16 per block; each block computes full N=256 for its row tiles, so
// A is read from gmem exactly ONCE. Warp tile 32x64 (16 warps = 4m x 4n).
// ---------------------------------------------------------------------------
#define GBM 128
#define GBK 32
#define APITCH 40               // halves; 20 words/row -> conflict-free frags
#define BPITCH 264              // halves; 132 words/row -> conflict-free frags
#define GTILES ((N_NODES + GBM - 1) / GBM)   // 782
#define GEMM_BLOCKS 148
#define GEMM_THREADS 512
#define GEMM_SMEM (GBM * APITCH * 2 + 256 * BPITCH * 2)   // 10240+135168 = 145408

__device__ __forceinline__ void mma_f16(float* c, uint32_t a0, uint32_t a1,
                                        uint32_t a2, uint32_t a3,
                                        uint32_t b0, uint32_t b1) {
    asm volatile(
        "mma.sync.aligned.m16n8k16.row.col.f32.f16.f16.f32 "
        "{%0,%1,%2,%3}, {%4,%5,%6,%7}, {%8,%9}, {%0,%1,%2,%3};"
        : "+f"(c[0]), "+f"(c[1]), "+f"(c[2]), "+f"(c[3])
        : "r"(a0), "r"(a1), "r"(a2), "r"(a3), "r"(b0), "r"(b1));
}

__global__ __launch_bounds__(GEMM_THREADS) void gemm_kernel(const float* __restrict__ A,
                                                            const float* __restrict__ W,
                                                            const float* __restrict__ bias) {
    extern __shared__ __half smem[];
    __half (*As)[APITCH] = reinterpret_cast<__half(*)[APITCH]>(smem);
    __half (*Bs)[BPITCH] = reinterpret_cast<__half(*)[BPITCH]>(smem + GBM * APITCH);

    const int tid = threadIdx.x;
    const int warp = tid >> 5;
    const int lane = tid & 31;
    const int wm = (warp & 3) * 32;      // 4 row groups of 32
    const int wn = (warp >> 2) * 64;     // 4 col groups of 64
    const int grp = lane >> 2;
    const int tig = lane & 3;

    // --- W preload: 256x256 fp32 -> Bs[n][k] fp16, once per block ---
    {
        int n  = tid & 255;
        int kh = (tid >> 8) * 128;       // 2 half-ranges of k
        for (int j = 0; j < 64; j++) {
            int k = kh + 2 * j;
            float w0 = __ldg(&W[(long long)k * FEATS + n]);
            float w1 = __ldg(&W[(long long)(k + 1) * FEATS + n]);
            *reinterpret_cast<__half2*>(&Bs[n][k]) = __floats2half2_rn(w0, w1);
        }
    }
    __syncthreads();

    for (int tile = blockIdx.x; tile < GTILES; tile += gridDim.x) {
        const int rowBase = tile * GBM;

        // Prologue: stage A chunk k0=0 (128 rows x 32 k = 1024 float4, 2/thread)
        float4 avs[2];
        #pragma unroll
        for (int s = 0; s < 2; s++) {
            int f = tid + s * 512;
            int ar = f >> 3, ac4 = (f & 7) * 4;
            int grow = rowBase + ar;
            avs[s] = make_float4(0.f, 0.f, 0.f, 0.f);
            if (grow < N_NODES)
                avs[s] = *reinterpret_cast<const float4*>(A + (long long)grow * FEATS + ac4);
        }

        float acc[2][8][4];
        #pragma unroll
        for (int i = 0; i < 2; i++)
            #pragma unroll
            for (int j = 0; j < 8; j++)
                #pragma unroll
                for (int k = 0; k < 4; k++) acc[i][j][k] = 0.f;

        for (int k0 = 0; k0 < FEATS; k0 += GBK) {
            #pragma unroll
            for (int s = 0; s < 2; s++) {
                int f = tid + s * 512;
                int ar = f >> 3, ac4 = (f & 7) * 4;
                __half2* ap = reinterpret_cast<__half2*>(&As[ar][ac4]);
                ap[0] = __floats2half2_rn(avs[s].x, avs[s].y);
                ap[1] = __floats2half2_rn(avs[s].z, avs[s].w);
            }
            __syncthreads();

            int kn = k0 + GBK;
            if (kn < FEATS) {
                #pragma unroll
                for (int s = 0; s < 2; s++) {
                    int f = tid + s * 512;
                    int ar = f >> 3, ac4 = (f & 7) * 4;
                    int grow = rowBase + ar;
                    avs[s] = make_float4(0.f, 0.f, 0.f, 0.f);
                    if (grow < N_NODES)
                        avs[s] = *reinterpret_cast<const float4*>(A + (long long)grow * FEATS + kn + ac4);
                }
            }

            #pragma unroll
            for (int ks = 0; ks < GBK; ks += 16) {
                uint32_t afr[2][4];
                #pragma unroll
                for (int mi = 0; mi < 2; mi++) {
                    int m = wm + mi * 16 + grp;
                    afr[mi][0] = *reinterpret_cast<const uint32_t*>(&As[m][ks + 2 * tig]);
                    afr[mi][1] = *reinterpret_cast<const uint32_t*>(&As[m + 8][ks + 2 * tig]);
                    afr[mi][2] = *reinterpret_cast<const uint32_t*>(&As[m][ks + 2 * tig + 8]);
                    afr[mi][3] = *reinterpret_cast<const uint32_t*>(&As[m + 8][ks + 2 * tig + 8]);
                }
                uint32_t bfr[8][2];
                #pragma unroll
                for (int ni = 0; ni < 8; ni++) {
                    int n = wn + ni * 8 + grp;
                    bfr[ni][0] = *reinterpret_cast<const uint32_t*>(&Bs[n][k0 + ks + 2 * tig]);
                    bfr[ni][1] = *reinterpret_cast<const uint32_t*>(&Bs[n][k0 + ks + 2 * tig + 8]);
                }
                #pragma unroll
                for (int mi = 0; mi < 2; mi++)
                    #pragma unroll
                    for (int ni = 0; ni < 8; ni++)
                        mma_f16(acc[mi][ni], afr[mi][0], afr[mi][1], afr[mi][2], afr[mi][3],
                                bfr[ni][0], bfr[ni][1]);
            }
            __syncthreads();
        }

        // Epilogue: add bias, write g_h as fp16
        #pragma unroll
        for (int mi = 0; mi < 2; mi++) {
            int row0 = rowBase + wm + mi * 16 + grp;
            int row1 = row0 + 8;
            #pragma unroll
            for (int ni = 0; ni < 8; ni++) {
                int col = wn + ni * 8 + 2 * tig;
                float b0 = __ldg(&bias[col]);
                float b1 = __ldg(&bias[col + 1]);
                if (row0 < N_NODES) {
                    __half2 v = __floats2half2_rn(acc[mi][ni][0] + b0, acc[mi][ni][1] + b1);
                    *reinterpret_cast<__half2*>(g_h + (long long)row0 * FEATS + col) = v;
                }
                if (row1 < N_NODES) {
                    __half2 v = __floats2half2_rn(acc[mi][ni][2] + b0, acc[mi][ni][3] + b1);
                    *reinterpret_cast<__half2*>(g_h + (long long)row1 * FEATS + col) = v;
                }
            }
        }
    }
}

// ---------------------------------------------------------------------------
// Gather-sum (R11 exact): one warp per node; lane owns 8 feats (uint4 fp16).
// ---------------------------------------------------------------------------
__device__ __forceinline__ void acc_uint4_h8(float* acc, uint4 v) {
    const __half2* hp = reinterpret_cast<const __half2*>(&v);
    #pragma unroll
    for (int q = 0; q < 4; q++) {
        float2 f = __half22float2(hp[q]);
        acc[2 * q]     += f.x;
        acc[2 * q + 1] += f.y;
    }
}

__global__ __launch_bounds__(256) void gather_kernel(float* __restrict__ out) {
    int node = blockIdx.x * 8 + (threadIdx.x >> 5);
    int lane = threadIdx.x & 31;
    if (node >= N_NODES) return;

    int deg = g_cnt[node];
    int n = deg < CAP ? deg : CAP;   // clamp (overflow statistically impossible)
    const int* __restrict__ cols = g_col + (long long)node * CAP;

    float acc[8] = {0.f, 0.f, 0.f, 0.f, 0.f, 0.f, 0.f, 0.f};

    int i = 0;
    for (; i + 3 < n; i += 4) {
        int c0 = __ldg(&cols[i]);
        int c1 = __ldg(&cols[i + 1]);
        int c2 = __ldg(&cols[i + 2]);
        int c3 = __ldg(&cols[i + 3]);
        uint4 v0 = __ldg(reinterpret_cast<const uint4*>(g_h + (long long)c0 * FEATS) + lane);
        uint4 v1 = __ldg(reinterpret_cast<const uint4*>(g_h + (long long)c1 * FEATS) + lane);
        uint4 v2 = __ldg(reinterpret_cast<const uint4*>(g_h + (long long)c2 * FEATS) + lane);
        uint4 v3 = __ldg(reinterpret_cast<const uint4*>(g_h + (long long)c3 * FEATS) + lane);
        acc_uint4_h8(acc, v0);
        acc_uint4_h8(acc, v1);
        acc_uint4_h8(acc, v2);
        acc_uint4_h8(acc, v3);
    }
    for (; i < n; i++) {
        int c0 = __ldg(&cols[i]);
        uint4 v0 = __ldg(reinterpret_cast<const uint4*>(g_h + (long long)c0 * FEATS) + lane);
        acc_uint4_h8(acc, v0);
    }

    float inv = deg > 0 ? 1.0f / (float)deg : 0.f;
    #pragma unroll
    for (int q = 0; q < 8; q++) acc[q] *= inv;

    float* dst = out + (long long)node * FEATS + lane * 8;
    float4 o0 = make_float4(acc[0], acc[1], acc[2], acc[3]);
    float4 o1 = make_float4(acc[4], acc[5], acc[6], acc[7]);
    __stcs(reinterpret_cast<float4*>(dst), o0);
    __stcs(reinterpret_cast<float4*>(dst) + 1, o1);
}

// ---------------------------------------------------------------------------
extern "C" void kernel_launch(void* const* d_in, const int* in_sizes, int n_in,
                              void* d_out, int out_size) {
    const float* x  = (const float*)d_in[0];
    const void*  ei = d_in[1];
    const float* W  = (const float*)d_in[2];
    const float* b  = (const float*)d_in[3];
    float* out = (float*)d_out;

    // Allow >48KB dynamic smem for the persistent GEMM (idempotent host call).
    cudaFuncSetAttribute(gemm_kernel, cudaFuncAttributeMaxDynamicSharedMemorySize,
                         GEMM_SMEM);

    zero_detect_kernel<<<(N_NODES + 255) / 256, 256>>>((const int*)ei);
    fill_kernel<<<1024, 256>>>(ei);
    gemm_kernel<<<GEMM_BLOCKS, GEMM_THREADS, GEMM_SMEM>>>(x, W, b);
    gather_kernel<<<(N_NODES + 7) / 8, 256>>>(out);
}